// round 11
// baseline (speedup 1.0000x reference)
#include <cuda_runtime.h>
#include <stdint.h>

// Problem constants
#define BB 16
#define CC 4
#define HH 512
#define WW 1024
#define ROWS (BB * CC * HH)       // 32768
#define NGRP (ROWS / 8)           // 4096 row-groups of 8 rows
#define BCN  (BB * CC)            // 64 (b,c) groups; 64 row-groups per bc
#define PBLK 1184                 // persistent grid: 148 SMs x 8 CTAs

// Per-(b,c) accumulators, padded to 128B stride to spread across L2 slices.
// [bc][0] = err sum, [bc][1] = cnt sum. Zero-initialized at module load; the
// finisher resets them after reading, so every graph replay sees zeros.
__device__ float g_acc[BCN][32];

// ---------------------------------------------------------------------------
// Kernel 1 (persistent streaming): R7 body verbatim, wrapped in a persistent
// loop over row-groups. One warp per row, 8 rows per iteration per block.
// Serial first-max compare chain (proven fastest), shared-mem 8-row reduce,
// two fire-and-forget REDG.ADDs per iteration. No with-return atomics, no
// polling.
// ---------------------------------------------------------------------------
__global__ __launch_bounds__(256) void row_argmax_kernel(
    const float* __restrict__ offset_pred,
    const float* __restrict__ offset_true,
    const float* __restrict__ cls_true,
    const float* __restrict__ vertical_true)
{
    const int warp_in_block = threadIdx.x >> 5;
    const int lane = threadIdx.x & 31;

    __shared__ float s_err[8];
    __shared__ float s_cnt[8];

    for (int g = blockIdx.x; g < NGRP; g += PBLK) {
        const int row = g * 8 + warp_in_block;

        const float4* crow =
            reinterpret_cast<const float4*>(cls_true + (size_t)row * WW);

        // Front-batch all 8 coalesced float4 loads (512B/warp each) -> MLP 8.
        float4 v[8];
#pragma unroll
        for (int k = 0; k < 8; k++) {
            v[k] = __ldcs(&crow[k * 32 + lane]);   // streaming: read-once
        }

        // Per-lane scan in increasing index order (first-max within lane).
        float best = -__int_as_float(0x7f800000);  // -inf
        int   bidx = 0;
#pragma unroll
        for (int k = 0; k < 8; k++) {
            const int base = (k * 32 + lane) * 4;
            if (v[k].x > best) { best = v[k].x; bidx = base + 0; }
            if (v[k].y > best) { best = v[k].y; bidx = base + 1; }
            if (v[k].z > best) { best = v[k].z; bidx = base + 2; }
            if (v[k].w > best) { best = v[k].w; bidx = base + 3; }
        }

        // Warp reduction: larger value wins; tie -> smaller index (first-max).
#pragma unroll
        for (int off = 16; off > 0; off >>= 1) {
            float oval = __shfl_xor_sync(0xffffffffu, best, off);
            int   oidx = __shfl_xor_sync(0xffffffffu, bidx, off);
            if (oval > best || (oval == best && oidx < bidx)) {
                best = oval;
                bidx = oidx;
            }
        }

        // Lane 0 of each warp: gather + mask for this row.
        if (lane == 0) {
            const size_t gidx = (size_t)row * WW + bidx;
            float p = __ldg(&offset_pred[gidx]);
            float t = __ldg(&offset_true[gidx]);
            float mask = (__ldg(&vertical_true[row]) >= 0.5f) ? 1.0f : 0.0f;
            s_err[warp_in_block] = fabsf(p - t) * mask;
            s_cnt[warp_in_block] = mask;
        }
        __syncthreads();

        // Warp 0, lanes 0..7 reduce the 8 row results; thread 0 fires two
        // REDs (no return -> REDG, no wait).
        if (threadIdx.x < 8) {
            float e = s_err[threadIdx.x];
            float c = s_cnt[threadIdx.x];
#pragma unroll
            for (int off = 4; off > 0; off >>= 1) {
                e += __shfl_xor_sync(0x000000ffu, e, off);
                c += __shfl_xor_sync(0x000000ffu, c, off);
            }
            if (threadIdx.x == 0) {
                const int bc = g >> 6;          // 64 row-groups per bc group
                atomicAdd(&g_acc[bc][0], e);    // REDG.ADD (result unused)
                atomicAdd(&g_acc[bc][1], c);
            }
        }
        __syncthreads();   // protect s_err/s_cnt reuse next iteration
    }
}

// ---------------------------------------------------------------------------
// Kernel 2 (finisher, PDL secondary): 64 threads read the 64 accumulator
// pairs (L2-hot), compute per-group means, reduce, write the scalar, and
// reset the accumulators for the next graph replay. R7-proven.
// ---------------------------------------------------------------------------
__global__ __launch_bounds__(64) void final_reduce_kernel(float* __restrict__ out)
{
#if __CUDA_ARCH__ >= 900
    cudaGridDependencySynchronize();
#endif

    const int t = threadIdx.x;   // 0..63

    float e = g_acc[t][0];
    float c = g_acc[t][1];
    float pbc = (c > 0.0f) ? (e / fmaxf(c, 1.0f)) : 0.0f;

    // Reset for the next replay (visible at kernel boundary).
    g_acc[t][0] = 0.0f;
    g_acc[t][1] = 0.0f;

    // Reduce 64 values across 2 warps.
    __shared__ float s_w[2];
#pragma unroll
    for (int off = 16; off > 0; off >>= 1) {
        pbc += __shfl_xor_sync(0xffffffffu, pbc, off);
    }
    if ((t & 31) == 0) s_w[t >> 5] = pbc;
    __syncthreads();

    if (t == 0) {
        out[0] = (s_w[0] + s_w[1]) / (float)BB;
    }
}

// ---------------------------------------------------------------------------
extern "C" void kernel_launch(void* const* d_in, const int* in_sizes, int n_in,
                              void* d_out, int out_size)
{
    const float* offset_pred   = (const float*)d_in[0];
    const float* offset_true   = (const float*)d_in[1];
    const float* cls_true      = (const float*)d_in[2];
    const float* vertical_true = (const float*)d_in[3];
    float* out = (float*)d_out;

    row_argmax_kernel<<<PBLK, 256>>>(offset_pred, offset_true, cls_true,
                                     vertical_true);

    // PDL finisher (R7-proven): overlaps launch latency with the primary.
    cudaLaunchAttribute attrs[1];
    attrs[0].id = cudaLaunchAttributeProgrammaticStreamSerialization;
    attrs[0].val.programmaticStreamSerializationAllowed = 1;

    cudaLaunchConfig_t cfg = {};
    cfg.gridDim = dim3(1, 1, 1);
    cfg.blockDim = dim3(64, 1, 1);
    cfg.dynamicSmemBytes = 0;
    cfg.stream = 0;
    cfg.attrs = attrs;
    cfg.numAttrs = 1;

    cudaLaunchKernelEx(&cfg, final_reduce_kernel, out);
}

// round 12
// speedup vs baseline: 1.0760x; 1.0760x over previous
#include <cuda_runtime.h>
#include <stdint.h>

// Problem constants
#define BB 16
#define CC 4
#define HH 512
#define WW 1024
#define ROWS (BB * CC * HH)       // 32768
#define NBLK (ROWS / 8)           // 4096 blocks, 8 rows each
#define BCN  (BB * CC)            // 64 (b,c) groups; 64 blocks per group

// Per-(b,c) reciprocal weights, padded to 128B lines. Recomputed by the
// prologue every launch — no reset needed for graph replays.
__device__ float g_inv[BCN][32];

// ---------------------------------------------------------------------------
// Kernel A (prologue): one block per (b,c) group. Counts masked rows in the
// group from vertical_true, stores inv[bc] = cnt>0 ? 1/(max(cnt,1)*B) : 0,
// and zeroes the output scalar. Triggers the dependent grid immediately so
// the main kernel streams concurrently with this one.
// ---------------------------------------------------------------------------
__global__ __launch_bounds__(512) void precompute_kernel(
    const float* __restrict__ vertical_true,
    float* __restrict__ out)
{
    if (threadIdx.x == 0) {
        asm volatile("griddepcontrol.launch_dependents;");
    }

    const int bc   = blockIdx.x;        // 0..63
    const int t    = threadIdx.x;       // 0..511
    const int lane = t & 31;
    const int wid  = t >> 5;

    float c = (__ldg(&vertical_true[bc * HH + t]) >= 0.5f) ? 1.0f : 0.0f;
#pragma unroll
    for (int off = 16; off > 0; off >>= 1) {
        c += __shfl_xor_sync(0xffffffffu, c, off);
    }

    __shared__ float s_c[16];
    if (lane == 0) s_c[wid] = c;
    __syncthreads();

    if (t == 0) {
        float cnt = 0.0f;
#pragma unroll
        for (int w = 0; w < 16; w++) cnt += s_c[w];
        g_inv[bc][0] = (cnt > 0.0f) ? (1.0f / (fmaxf(cnt, 1.0f) * (float)BB))
                                    : 0.0f;
        if (bc == 0) out[0] = 0.0f;
    }
}

// ---------------------------------------------------------------------------
// Kernel B (main, PDL dependent): exact R7 streaming body. One warp per row,
// 8 rows per block. Argmax over W=1024 (first-max), gather offsets, mask,
// smem-reduce the 8 rows; thread 0 then waits on the (long-satisfied) grid
// dependency, scales by inv[bc], and fires ONE fire-and-forget RED into out.
// ---------------------------------------------------------------------------
__global__ __launch_bounds__(256) void row_argmax_kernel(
    const float* __restrict__ offset_pred,
    const float* __restrict__ offset_true,
    const float* __restrict__ cls_true,
    const float* __restrict__ vertical_true,
    float* __restrict__ out)
{
    const int warp_in_block = threadIdx.x >> 5;
    const int lane = threadIdx.x & 31;
    const int row = blockIdx.x * 8 + warp_in_block;

    const float4* crow = reinterpret_cast<const float4*>(cls_true + (size_t)row * WW);

    // Front-batch all 8 coalesced float4 loads (512B/warp each) -> MLP 8.
    float4 v[8];
#pragma unroll
    for (int k = 0; k < 8; k++) {
        v[k] = __ldcs(&crow[k * 32 + lane]);   // streaming: read-once data
    }

    // Per-lane scan in increasing index order (first-max within lane).
    float best = -__int_as_float(0x7f800000);  // -inf
    int   bidx = 0;
#pragma unroll
    for (int k = 0; k < 8; k++) {
        const int base = (k * 32 + lane) * 4;
        if (v[k].x > best) { best = v[k].x; bidx = base + 0; }
        if (v[k].y > best) { best = v[k].y; bidx = base + 1; }
        if (v[k].z > best) { best = v[k].z; bidx = base + 2; }
        if (v[k].w > best) { best = v[k].w; bidx = base + 3; }
    }

    // Warp reduction: larger value wins; exact tie -> smaller index (first-max).
#pragma unroll
    for (int off = 16; off > 0; off >>= 1) {
        float oval = __shfl_xor_sync(0xffffffffu, best, off);
        int   oidx = __shfl_xor_sync(0xffffffffu, bidx, off);
        if (oval > best || (oval == best && oidx < bidx)) {
            best = oval;
            bidx = oidx;
        }
    }

    // Lane 0 of each warp: gather + mask for this row.
    __shared__ float s_err[8];
    if (lane == 0) {
        const size_t gidx = (size_t)row * WW + bidx;
        float p = __ldg(&offset_pred[gidx]);
        float t = __ldg(&offset_true[gidx]);
        float mask = (__ldg(&vertical_true[row]) >= 0.5f) ? 1.0f : 0.0f;
        s_err[warp_in_block] = fabsf(p - t) * mask;
    }
    __syncthreads();

    // Warp 0, lanes 0..7 reduce the 8 row errors; thread 0 scales by the
    // precomputed reciprocal and fires one REDG.ADD into the output.
    if (threadIdx.x < 8) {
        float e = s_err[threadIdx.x];
#pragma unroll
        for (int off = 4; off > 0; off >>= 1) {
            e += __shfl_xor_sync(0x000000ffu, e, off);
        }
        if (threadIdx.x == 0) {
#if __CUDA_ARCH__ >= 900
            cudaGridDependencySynchronize();   // satisfied ~20us ago: free
#endif
            const int bc = blockIdx.x >> 6;    // 64 blocks per group
            atomicAdd(out, e * g_inv[bc][0]);  // REDG.ADD (result unused)
        }
    }
}

// ---------------------------------------------------------------------------
extern "C" void kernel_launch(void* const* d_in, const int* in_sizes, int n_in,
                              void* d_out, int out_size)
{
    const float* offset_pred   = (const float*)d_in[0];
    const float* offset_true   = (const float*)d_in[1];
    const float* cls_true      = (const float*)d_in[2];
    const float* vertical_true = (const float*)d_in[3];
    float* out = (float*)d_out;

    // Prologue (primary): computes per-group reciprocals + zeroes out.
    precompute_kernel<<<BCN, 512>>>(vertical_true, out);

    // Main kernel (PDL dependent): launches while the prologue runs; its
    // device-side gridDependencySynchronize (at the very tail) is satisfied
    // long before it executes.
    cudaLaunchAttribute attrs[1];
    attrs[0].id = cudaLaunchAttributeProgrammaticStreamSerialization;
    attrs[0].val.programmaticStreamSerializationAllowed = 1;

    cudaLaunchConfig_t cfg = {};
    cfg.gridDim = dim3(NBLK, 1, 1);
    cfg.blockDim = dim3(256, 1, 1);
    cfg.dynamicSmemBytes = 0;
    cfg.stream = 0;
    cfg.attrs = attrs;
    cfg.numAttrs = 1;

    cudaLaunchKernelEx(&cfg, row_argmax_kernel,
                       offset_pred, offset_true, cls_true, vertical_true, out);
}

// round 13
// speedup vs baseline: 1.0862x; 1.0094x over previous
#include <cuda_runtime.h>
#include <stdint.h>

// Problem constants
#define BB 16
#define CC 4
#define HH 512
#define WW 1024
#define ROWS (BB * CC * HH)       // 32768
#define NBLK (ROWS / 8)           // 4096 blocks, 8 rows each
#define BCN  (BB * CC)            // 64 (b,c) groups; 64 blocks per group

// ---------------------------------------------------------------------------
// Kernel A (primary, 1 block / 32 threads): zero the output scalar, release-
// fence, THEN trigger the dependent grid. Per the PDL contract, writes made
// before griddepcontrol.launch_dependents (with a gpu-scope fence) are
// visible to the dependent grid — so kernel B needs NO acquire at all.
// ---------------------------------------------------------------------------
__global__ void zero_out_kernel(float* __restrict__ out)
{
    if (threadIdx.x == 0) {
        out[0] = 0.0f;
        __threadfence();   // release: order the store before the trigger
        asm volatile("griddepcontrol.launch_dependents;");
    }
}

// ---------------------------------------------------------------------------
// Kernel B (dependent, streaming): exact R7 body — one warp per row, 8 rows
// per block, serial first-max argmax, one __syncthreads, fire-and-forget
// RED at the tail. Warp 0 additionally recomputes its (b,c) group's masked
// row count from L2-resident vertical_true (2 KB), so no cross-kernel state
// and no per-block acquire is needed. NO gridDependencySynchronize, NO
// fences, NO with-return atomics.
// ---------------------------------------------------------------------------
__global__ __launch_bounds__(256) void row_argmax_kernel(
    const float* __restrict__ offset_pred,
    const float* __restrict__ offset_true,
    const float* __restrict__ cls_true,
    const float* __restrict__ vertical_true,
    float* __restrict__ out)
{
    const int warp_in_block = threadIdx.x >> 5;
    const int lane = threadIdx.x & 31;
    const int row = blockIdx.x * 8 + warp_in_block;

    const float4* crow = reinterpret_cast<const float4*>(cls_true + (size_t)row * WW);

    // Front-batch all 8 coalesced float4 loads (512B/warp each) -> MLP 8.
    float4 v[8];
#pragma unroll
    for (int k = 0; k < 8; k++) {
        v[k] = __ldcs(&crow[k * 32 + lane]);   // streaming: read-once data
    }

    // Per-lane scan in increasing index order (first-max within lane).
    float best = -__int_as_float(0x7f800000);  // -inf
    int   bidx = 0;
#pragma unroll
    for (int k = 0; k < 8; k++) {
        const int base = (k * 32 + lane) * 4;
        if (v[k].x > best) { best = v[k].x; bidx = base + 0; }
        if (v[k].y > best) { best = v[k].y; bidx = base + 1; }
        if (v[k].z > best) { best = v[k].z; bidx = base + 2; }
        if (v[k].w > best) { best = v[k].w; bidx = base + 3; }
    }

    // Warp reduction: larger value wins; exact tie -> smaller index (first-max).
#pragma unroll
    for (int off = 16; off > 0; off >>= 1) {
        float oval = __shfl_xor_sync(0xffffffffu, best, off);
        int   oidx = __shfl_xor_sync(0xffffffffu, bidx, off);
        if (oval > best || (oval == best && oidx < bidx)) {
            best = oval;
            bidx = oidx;
        }
    }

    // Lane 0 of each warp: gather + mask for this row.
    __shared__ float s_err[8];
    if (lane == 0) {
        const size_t gidx = (size_t)row * WW + bidx;
        float p = __ldg(&offset_pred[gidx]);
        float t = __ldg(&offset_true[gidx]);
        float mask = (__ldg(&vertical_true[row]) >= 0.5f) ? 1.0f : 0.0f;
        s_err[warp_in_block] = fabsf(p - t) * mask;
    }
    __syncthreads();

    // Warp 0 tail: recompute the group's masked-row count (512 floats, L2-hot)
    // and reduce the block's 8 row errors; thread 0 fires ONE REDG.ADD.
    if (warp_in_block == 0) {
        const int bc = blockIdx.x >> 6;        // 64 blocks per (b,c) group
        const float4* vt =
            reinterpret_cast<const float4*>(vertical_true + bc * HH);

        float cnt = 0.0f;
#pragma unroll
        for (int j = 0; j < 4; j++) {
            float4 w = __ldg(&vt[j * 32 + lane]);
            cnt += (w.x >= 0.5f) ? 1.0f : 0.0f;
            cnt += (w.y >= 0.5f) ? 1.0f : 0.0f;
            cnt += (w.z >= 0.5f) ? 1.0f : 0.0f;
            cnt += (w.w >= 0.5f) ? 1.0f : 0.0f;
        }
#pragma unroll
        for (int off = 16; off > 0; off >>= 1) {
            cnt += __shfl_xor_sync(0xffffffffu, cnt, off);
        }

        float e = (lane < 8) ? s_err[lane] : 0.0f;
#pragma unroll
        for (int off = 4; off > 0; off >>= 1) {
            e += __shfl_xor_sync(0xffffffffu, e, off);
        }

        if (lane == 0) {
            const float scale = (cnt > 0.0f)
                ? (1.0f / (fmaxf(cnt, 1.0f) * (float)BB)) : 0.0f;
            atomicAdd(out, e * scale);         // REDG.ADD (result unused)
        }
    }
}

// ---------------------------------------------------------------------------
extern "C" void kernel_launch(void* const* d_in, const int* in_sizes, int n_in,
                              void* d_out, int out_size)
{
    const float* offset_pred   = (const float*)d_in[0];
    const float* offset_true   = (const float*)d_in[1];
    const float* cls_true      = (const float*)d_in[2];
    const float* vertical_true = (const float*)d_in[3];
    float* out = (float*)d_out;

    // Primary: zero the scalar, release-fence, trigger dependents.
    zero_out_kernel<<<1, 32>>>(out);

    // Dependent: the full streaming kernel; launches while the primary's
    // ~1us node is still in flight, so the zero node costs ~nothing.
    cudaLaunchAttribute attrs[1];
    attrs[0].id = cudaLaunchAttributeProgrammaticStreamSerialization;
    attrs[0].val.programmaticStreamSerializationAllowed = 1;

    cudaLaunchConfig_t cfg = {};
    cfg.gridDim = dim3(NBLK, 1, 1);
    cfg.blockDim = dim3(256, 1, 1);
    cfg.dynamicSmemBytes = 0;
    cfg.stream = 0;
    cfg.attrs = attrs;
    cfg.numAttrs = 1;

    cudaLaunchKernelEx(&cfg, row_argmax_kernel,
                       offset_pred, offset_true, cls_true, vertical_true, out);
}